// round 8
// baseline (speedup 1.0000x reference)
#include <cuda_runtime.h>

#define T25   25
#define HID   100
#define G4    400
#define NROWS 12800           // 512*25
#define RB    8               // batch rows per rec block
#define RNB   64              // rec blocks

typedef unsigned long long u64;

__device__ float g_zx1[(size_t)NROWS * G4];
__device__ float g_z2x[(size_t)NROWS * G4];
__device__ float g_h1 [(size_t)NROWS * HID];

union U4 { float4 f4; ulonglong2 u2; };
union U2 { float2 f2; u64 u; };

__device__ __forceinline__ u64 pk(float lo, float hi) {
    u64 r; asm("mov.b64 %0, {%1,%2};" : "=l"(r) : "f"(lo), "f"(hi)); return r;
}
__device__ __forceinline__ void ffma2(u64& d, u64 a, u64 b) {
    asm("fma.rn.f32x2 %0, %1, %2, %0;" : "+l"(d) : "l"(a), "l"(b));
}
__device__ __forceinline__ float hsum(u64 v) {
    float a, b; asm("mov.b64 {%0,%1}, %2;" : "=f"(a), "=f"(b) : "l"(v)); return a + b;
}
__device__ __forceinline__ float sigm(float x)   { return 1.0f / (1.0f + __expf(-x)); }
__device__ __forceinline__ float mytanh(float x) { float e = __expf(-2.0f * x); return (1.0f - e) / (1.0f + e); }

// ---------------------------------------------------------------------------
// Input-projection GEMM (unchanged from 227 µs config).
// ---------------------------------------------------------------------------
#define IP_SMEM_B ((HID * G4 + HID * 104) * 4)   // 201600 bytes

template<int NQ>
__device__ __forceinline__ void inproj_main(
    const float (*xs)[104], const float* __restrict__ wsm,
    int c, int rb, float bv, float* __restrict__ out, int row0)
{
    u64 acc[2 * NQ];
    u64 binit = pk(bv, bv);
    #pragma unroll
    for (int p = 0; p < 2 * NQ; p++) acc[p] = binit;

    #pragma unroll 2
    for (int k = 0; k < HID; k++) {
        float w = wsm[k * G4 + c];
        u64 wd = pk(w, w);
        const float* xr = &xs[k][rb];
        #pragma unroll
        for (int q = 0; q < NQ; q++) {
            U4 x; x.f4 = *(const float4*)(xr + 4 * q);
            ffma2(acc[2 * q],     x.u2.x, wd);
            ffma2(acc[2 * q + 1], x.u2.y, wd);
        }
    }
    #pragma unroll
    for (int p = 0; p < 2 * NQ; p++) {
        U2 v; v.u = acc[p];
        out[(long long)(row0 + rb + 2 * p) * G4 + c]     = v.f2.x;
        out[(long long)(row0 + rb + 2 * p + 1) * G4 + c] = v.f2.y;
    }
}

__global__ void __launch_bounds__(800, 1) inproj_kernel(
    const float* __restrict__ src, const int* __restrict__ feats,
    const float* __restrict__ emb, const float* __restrict__ W,
    const float* __restrict__ bias, float* __restrict__ out)
{
    extern __shared__ __align__(16) float smp[];
    float* wsm = smp;
    float (*xs)[104] = (float(*)[104])(smp + HID * G4);

    const int tid  = threadIdx.x;
    const int row0 = blockIdx.x * 100;

    for (int i4 = tid; i4 < HID * G4 / 4; i4 += 800)
        ((float4*)wsm)[i4] = ((const float4*)W)[i4];

    for (int idx = tid; idx < 25 * 100; idx += 800) {
        int j4 = idx / 100, rl = idx % 100;
        const float* base = feats
            ? emb + (long long)__ldg(feats + row0 + rl) * HID
            : src + (long long)(row0 + rl) * HID;
        float4 v = *(const float4*)(base + 4 * j4);
        xs[4 * j4 + 0][rl] = v.x;
        xs[4 * j4 + 1][rl] = v.y;
        xs[4 * j4 + 2][rl] = v.z;
        xs[4 * j4 + 3][rl] = v.w;
    }
    __syncthreads();

    const int c  = tid % G4;
    const int rg = tid / G4;
    const float bv = bias[c];
    if (rg == 0) inproj_main<13>(xs, wsm, c, 0,  bv, out, row0);
    else         inproj_main<12>(xs, wsm, c, 52, bv, out, row0);
}

// ---------------------------------------------------------------------------
// Recurrence kernel: R3 structure scaled to 8 batch rows per block.
// 64 blocks, 800 threads = 400 cols x 2 k-halves, weights in regs (26 u64).
// 8 named u64 accumulators; zp smem reduction; 2 barriers/step (fixed cost
// amortized over 2x GEMM work vs the 79us 4-row version).
// ---------------------------------------------------------------------------
__global__ void __launch_bounds__(800, 1) rec_kernel(
    const float* __restrict__ zin,    // [12800][400]
    const float* __restrict__ Wh,     // [100][400]
    float*       __restrict__ h_out,  // [12800][100] or null
    const float* __restrict__ wfc1, const float* __restrict__ bfc1,
    const float* __restrict__ wfc2, const float* __restrict__ bfc2,
    float*       __restrict__ out)    // [512][2] or null
{
    __shared__ __align__(16) float hs[RB][104];     // rows 0-7, zero-padded k
    __shared__ float zp[2][RB][G4];                 // [khalf][row][col]
    __shared__ float fc1s[RB][128];

    const int tid = threadIdx.x;
    const int b0  = blockIdx.x * RB;
    const int c   = tid % G4;
    const int kh  = tid / G4;

    u64 wp[26];
    #pragma unroll
    for (int j = 0; j < 26; j++) {
        int k = kh * 52 + 2 * j;
        float w0 = (k     < HID) ? __ldg(Wh + (k    ) * G4 + c) : 0.f;
        float w1 = (k + 1 < HID) ? __ldg(Wh + (k + 1) * G4 + c) : 0.f;
        wp[j] = pk(w0, w1);
    }
    for (int i = tid; i < RB * 104; i += 800) ((float*)hs)[i] = 0.f;
    __syncthreads();

    const int ur = tid / 100;    // gate row-pair id (valid tid < 400): rows 2ur,2ur+1
    const int gu = tid % 100;
    float csA = 0.f, csB = 0.f;  // cell states for rows 2ur, 2ur+1

    for (int t = 0; t < T25; t++) {
        // ---- prefetch this step's zin for the gate phase (consumed after barrier)
        float zA0=0.f,zA1=0.f,zA2=0.f,zA3=0.f, zB0=0.f,zB1=0.f,zB2=0.f,zB3=0.f;
        if (tid < 400) {
            const float* zrA = zin + ((long long)(b0 + 2*ur    ) * T25 + t) * G4 + gu;
            const float* zrB = zin + ((long long)(b0 + 2*ur + 1) * T25 + t) * G4 + gu;
            zA0 = __ldg(zrA);       zB0 = __ldg(zrB);
            zA1 = __ldg(zrA + 100); zB1 = __ldg(zrB + 100);
            zA2 = __ldg(zrA + 200); zB2 = __ldg(zrB + 200);
            zA3 = __ldg(zrA + 300); zB3 = __ldg(zrB + 300);
        }

        // ---- GEMM over my k half, 8 rows, named accumulators ----
        u64 a0=0ULL,a1=0ULL,a2=0ULL,a3=0ULL,a4=0ULL,a5=0ULL,a6=0ULL,a7=0ULL;
        const int kb = kh * 52;
        #pragma unroll
        for (int j4 = 0; j4 < 13; j4++) {
            U4 v;
            v.f4 = *(const float4*)&hs[0][kb + 4*j4];
            ffma2(a0, v.u2.x, wp[2*j4]); ffma2(a0, v.u2.y, wp[2*j4+1]);
            v.f4 = *(const float4*)&hs[1][kb + 4*j4];
            ffma2(a1, v.u2.x, wp[2*j4]); ffma2(a1, v.u2.y, wp[2*j4+1]);
            v.f4 = *(const float4*)&hs[2][kb + 4*j4];
            ffma2(a2, v.u2.x, wp[2*j4]); ffma2(a2, v.u2.y, wp[2*j4+1]);
            v.f4 = *(const float4*)&hs[3][kb + 4*j4];
            ffma2(a3, v.u2.x, wp[2*j4]); ffma2(a3, v.u2.y, wp[2*j4+1]);
            v.f4 = *(const float4*)&hs[4][kb + 4*j4];
            ffma2(a4, v.u2.x, wp[2*j4]); ffma2(a4, v.u2.y, wp[2*j4+1]);
            v.f4 = *(const float4*)&hs[5][kb + 4*j4];
            ffma2(a5, v.u2.x, wp[2*j4]); ffma2(a5, v.u2.y, wp[2*j4+1]);
            v.f4 = *(const float4*)&hs[6][kb + 4*j4];
            ffma2(a6, v.u2.x, wp[2*j4]); ffma2(a6, v.u2.y, wp[2*j4+1]);
            v.f4 = *(const float4*)&hs[7][kb + 4*j4];
            ffma2(a7, v.u2.x, wp[2*j4]); ffma2(a7, v.u2.y, wp[2*j4+1]);
        }
        zp[kh][0][c] = hsum(a0);
        zp[kh][1][c] = hsum(a1);
        zp[kh][2][c] = hsum(a2);
        zp[kh][3][c] = hsum(a3);
        zp[kh][4][c] = hsum(a4);
        zp[kh][5][c] = hsum(a5);
        zp[kh][6][c] = hsum(a6);
        zp[kh][7][c] = hsum(a7);
        __syncthreads();

        // ---- gates: 400 threads x 2 rows each ----
        if (tid < 400) {
            const int rA = 2 * ur, rB = 2 * ur + 1;
            float zi = zA0 + zp[0][rA][gu]       + zp[1][rA][gu];
            float zj = zA1 + zp[0][rA][gu + 100] + zp[1][rA][gu + 100];
            float zf = zA2 + zp[0][rA][gu + 200] + zp[1][rA][gu + 200];
            float zo = zA3 + zp[0][rA][gu + 300] + zp[1][rA][gu + 300];
            csA = csA * sigm(zf + 1.0f) + sigm(zi) * mytanh(zj);
            float hA = mytanh(csA) * sigm(zo);
            hs[rA][gu] = hA;

            zi = zB0 + zp[0][rB][gu]       + zp[1][rB][gu];
            zj = zB1 + zp[0][rB][gu + 100] + zp[1][rB][gu + 100];
            zf = zB2 + zp[0][rB][gu + 200] + zp[1][rB][gu + 200];
            zo = zB3 + zp[0][rB][gu + 300] + zp[1][rB][gu + 300];
            csB = csB * sigm(zf + 1.0f) + sigm(zi) * mytanh(zj);
            float hB = mytanh(csB) * sigm(zo);
            hs[rB][gu] = hB;

            if (h_out) {
                h_out[((long long)(b0 + rA) * T25 + t) * HID + gu] = hA;
                h_out[((long long)(b0 + rB) * T25 + t) * HID + gu] = hB;
            }
        }
        __syncthreads();
    }

    // ---- FC head (layer-2 kernel only) ----
    if (out) {
        for (int idx = tid; idx < RB * 128; idx += 800) {
            int r = idx / 128, j = idx % 128;
            float a = bfc1[j];
            #pragma unroll 4
            for (int k = 0; k < HID; k++)
                a += hs[r][k] * __ldg(wfc1 + k * 128 + j);
            fc1s[r][j] = a;
        }
        __syncthreads();
        if (tid < RB * 2) {
            int r = tid / 2, cc = tid % 2;
            float a = bfc2[cc];
            #pragma unroll 8
            for (int k = 0; k < 128; k++)
                a += fc1s[r][k] * __ldg(wfc2 + k * 2 + cc);
            out[(b0 + r) * 2 + cc] = a;
        }
    }
}

// ---------------------------------------------------------------------------
extern "C" void kernel_launch(void* const* d_in, const int* in_sizes, int n_in,
                              void* d_out, int out_size)
{
    const int*   feats = (const int*)  d_in[0];
    const float* emb   = (const float*)d_in[1];
    const float* k1    = (const float*)d_in[2];
    const float* b1    = (const float*)d_in[3];
    const float* k2    = (const float*)d_in[4];
    const float* b2    = (const float*)d_in[5];
    const float* wfc1  = (const float*)d_in[6];
    const float* bfc1  = (const float*)d_in[7];
    const float* wfc2  = (const float*)d_in[8];
    const float* bfc2  = (const float*)d_in[9];
    float* out = (float*)d_out;

    float *zx1, *z2x, *h1;
    cudaGetSymbolAddress((void**)&zx1, g_zx1);
    cudaGetSymbolAddress((void**)&z2x, g_z2x);
    cudaGetSymbolAddress((void**)&h1,  g_h1);

    cudaFuncSetAttribute(inproj_kernel,
                         cudaFuncAttributeMaxDynamicSharedMemorySize, IP_SMEM_B);

    inproj_kernel<<<128, 800, IP_SMEM_B>>>(nullptr, feats, emb, k1, b1, zx1);
    rec_kernel<<<RNB, 800>>>(zx1, k1 + HID * G4, h1,
                             nullptr, nullptr, nullptr, nullptr, nullptr);
    inproj_kernel<<<128, 800, IP_SMEM_B>>>(h1, nullptr, nullptr, k2, b2, z2x);
    rec_kernel<<<RNB, 800>>>(z2x, k2 + HID * G4, nullptr,
                             wfc1, bfc1, wfc2, bfc2, out);
}

// round 9
// speedup vs baseline: 1.6398x; 1.6398x over previous
#include <cuda_runtime.h>

#define T25   25
#define HID   100
#define G4    400
#define NROWS 12800           // 512*25

typedef unsigned long long u64;

__device__ float g_zx1[(size_t)NROWS * G4];   // layer1 input projection (incl b1)
__device__ float g_z2x[(size_t)NROWS * G4];   // layer2 input projection (incl b2)

union U4 { float4 f4; ulonglong2 u2; };
union U2 { float2 f2; u64 u; };

__device__ __forceinline__ u64 pk(float lo, float hi) {
    u64 r; asm("mov.b64 %0, {%1,%2};" : "=l"(r) : "f"(lo), "f"(hi)); return r;
}
__device__ __forceinline__ void ffma2(u64& d, u64 a, u64 b) {
    asm("fma.rn.f32x2 %0, %1, %2, %0;" : "+l"(d) : "l"(a), "l"(b));
}
__device__ __forceinline__ float hsum(u64 v) {
    float a, b; asm("mov.b64 {%0,%1}, %2;" : "=f"(a), "=f"(b) : "l"(v)); return a + b;
}
__device__ __forceinline__ float sigm(float x)   { return 1.0f / (1.0f + __expf(-x)); }
__device__ __forceinline__ float mytanh(float x) { float e = __expf(-2.0f * x); return (1.0f - e) / (1.0f + e); }

// ---------------------------------------------------------------------------
// Input-projection GEMM (R6 config, 28us): out[row][c] = b[c] + src(row)@W[:,c]
// ---------------------------------------------------------------------------
#define IP_SMEM_B ((HID * G4 + HID * 104) * 4)   // 201600 bytes

template<int NQ>
__device__ __forceinline__ void inproj_main(
    const float (*xs)[104], const float* __restrict__ wsm,
    int c, int rb, float bv, float* __restrict__ out, int row0)
{
    u64 acc[2 * NQ];
    u64 binit = pk(bv, bv);
    #pragma unroll
    for (int p = 0; p < 2 * NQ; p++) acc[p] = binit;

    #pragma unroll 2
    for (int k = 0; k < HID; k++) {
        float w = wsm[k * G4 + c];
        u64 wd = pk(w, w);
        const float* xr = &xs[k][rb];
        #pragma unroll
        for (int q = 0; q < NQ; q++) {
            U4 x; x.f4 = *(const float4*)(xr + 4 * q);
            ffma2(acc[2 * q],     x.u2.x, wd);
            ffma2(acc[2 * q + 1], x.u2.y, wd);
        }
    }
    #pragma unroll
    for (int p = 0; p < 2 * NQ; p++) {
        U2 v; v.u = acc[p];
        out[(long long)(row0 + rb + 2 * p) * G4 + c]     = v.f2.x;
        out[(long long)(row0 + rb + 2 * p + 1) * G4 + c] = v.f2.y;
    }
}

__global__ void __launch_bounds__(800, 1) inproj_kernel(
    const int*   __restrict__ feats,  // [12800]
    const float* __restrict__ emb,    // [VOCAB][100]
    const float* __restrict__ W,      // [100][400]
    const float* __restrict__ bias,   // [400]
    float*       __restrict__ out)    // [12800][400]
{
    extern __shared__ __align__(16) float smp[];
    float* wsm = smp;
    float (*xs)[104] = (float(*)[104])(smp + HID * G4);

    const int tid  = threadIdx.x;
    const int row0 = blockIdx.x * 100;

    for (int i4 = tid; i4 < HID * G4 / 4; i4 += 800)
        ((float4*)wsm)[i4] = ((const float4*)W)[i4];

    for (int idx = tid; idx < 25 * 100; idx += 800) {
        int j4 = idx / 100, rl = idx % 100;
        const float* base = emb + (long long)__ldg(feats + row0 + rl) * HID;
        float4 v = *(const float4*)(base + 4 * j4);
        xs[4 * j4 + 0][rl] = v.x;
        xs[4 * j4 + 1][rl] = v.y;
        xs[4 * j4 + 2][rl] = v.z;
        xs[4 * j4 + 3][rl] = v.w;
    }
    __syncthreads();

    const int c  = tid % G4;
    const int rg = tid / G4;
    const float bv = bias[c];
    if (rg == 0) inproj_main<13>(xs, wsm, c, 0,  bv, out, row0);
    else         inproj_main<12>(xs, wsm, c, 52, bv, out, row0);
}

// ---------------------------------------------------------------------------
// Recurrence kernel (exact R3 79us structure). FUSE variant additionally
// computes z2x[t] = h1[t] @ Wx2 + b2 right after each step's gates, using
// smem-staged pre-paired Wx2 (fire-and-forget side output, no new barrier).
// 128 blocks x 4 rows, 800 threads = 400 cols x 2 k-halves, Wh in registers.
// ---------------------------------------------------------------------------
#define HS_BYTES   (4 * 104 * 4)          // 1664
#define ZP_BYTES   (2 * 4 * G4 * 4)       // 12800
#define FC_BYTES   (4 * 128 * 4)          // 2048
#define WQ_BYTES   (25 * G4 * 16)         // 160000
#define SM_PLAIN   (HS_BYTES + ZP_BYTES + FC_BYTES)            // 16512
#define SM_FUSE    (WQ_BYTES + HS_BYTES + ZP_BYTES)            // 174464

template<bool FUSE>
__global__ void __launch_bounds__(800, 1) rec_kernel(
    const float* __restrict__ zin,    // [12800][400]  (x-proj incl bias)
    const float* __restrict__ Wh,     // [100][400]
    const float* __restrict__ Wx2,    // FUSE: k2[0:100][400]
    const float* __restrict__ b2,     // FUSE: [400]
    float*       __restrict__ zx_out, // FUSE: [12800][400]
    const float* __restrict__ wfc1, const float* __restrict__ bfc1,
    const float* __restrict__ wfc2, const float* __restrict__ bfc2,
    float*       __restrict__ out)    // [512][2] or null
{
    extern __shared__ __align__(16) char dynsm[];
    ulonglong2* wq = (ulonglong2*)dynsm;                         // [25*400] iff FUSE
    const int wqb = FUSE ? WQ_BYTES : 0;
    float (*hs)[104] = (float(*)[104])(dynsm + wqb);
    float (*zp)[4][G4] = (float(*)[4][G4])(dynsm + wqb + HS_BYTES);
    float (*fc1s)[128] = (float(*)[128])(dynsm + wqb + HS_BYTES + ZP_BYTES);

    const int tid = threadIdx.x;
    const int b0  = blockIdx.x * 4;
    const int c   = tid % G4;
    const int kh  = tid / G4;                        // k half: 0 or 1

    // preload my 52 recurrent weights
    u64 wp[26];
    #pragma unroll
    for (int j = 0; j < 26; j++) {
        int k = kh * 52 + 2 * j;
        float w0 = (k     < HID) ? __ldg(Wh + (k    ) * G4 + c) : 0.f;
        float w1 = (k + 1 < HID) ? __ldg(Wh + (k + 1) * G4 + c) : 0.f;
        wp[j] = pk(w0, w1);
    }
    // stage Wx2 pre-paired (FUSE only)
    if (FUSE) {
        for (int idx = tid; idx < 25 * G4; idx += 800) {
            int q = idx / G4, cc = idx % G4;
            const float* ws = Wx2 + (4 * q) * G4 + cc;
            ulonglong2 wv;
            wv.x = pk(ws[0],      ws[G4]);
            wv.y = pk(ws[2 * G4], ws[3 * G4]);
            wq[idx] = wv;
        }
    }
    for (int i = tid; i < 4 * 104; i += 800) ((float*)hs)[i] = 0.f;
    __syncthreads();

    const int gr = tid / 100;    // gate row (valid for tid < 400)
    const int gu = tid % 100;
    float cst = 0.f;
    const float bv = FUSE ? __ldg(b2 + c) : 0.f;

    for (int t = 0; t < T25; t++) {
        // ---- prefetch this step's zin for the gate phase ----
        float zx0 = 0.f, zx1 = 0.f, zx2 = 0.f, zx3 = 0.f;
        if (tid < 400) {
            const float* zr = zin + ((long long)(b0 + gr) * T25 + t) * G4;
            zx0 = __ldg(zr + gu);
            zx1 = __ldg(zr + gu + 100);
            zx2 = __ldg(zr + gu + 200);
            zx3 = __ldg(zr + gu + 300);
        }

        // ---- GEMM over my k half ----
        u64 a0 = 0ULL, a1 = 0ULL, a2 = 0ULL, a3 = 0ULL;
        const int kb = kh * 52;
        #pragma unroll
        for (int j4 = 0; j4 < 13; j4++) {
            U4 v0; v0.f4 = *(const float4*)&hs[0][kb + 4 * j4];
            U4 v1; v1.f4 = *(const float4*)&hs[1][kb + 4 * j4];
            U4 v2; v2.f4 = *(const float4*)&hs[2][kb + 4 * j4];
            U4 v3; v3.f4 = *(const float4*)&hs[3][kb + 4 * j4];
            ffma2(a0, v0.u2.x, wp[2 * j4]);
            ffma2(a0, v0.u2.y, wp[2 * j4 + 1]);
            ffma2(a1, v1.u2.x, wp[2 * j4]);
            ffma2(a1, v1.u2.y, wp[2 * j4 + 1]);
            ffma2(a2, v2.u2.x, wp[2 * j4]);
            ffma2(a2, v2.u2.y, wp[2 * j4 + 1]);
            ffma2(a3, v3.u2.x, wp[2 * j4]);
            ffma2(a3, v3.u2.y, wp[2 * j4 + 1]);
        }
        zp[kh][0][c] = hsum(a0);
        zp[kh][1][c] = hsum(a1);
        zp[kh][2][c] = hsum(a2);
        zp[kh][3][c] = hsum(a3);
        __syncthreads();

        // ---- gates (tid < 400) ----
        if (tid < 400) {
            float zi = zx0 + zp[0][gr][gu]       + zp[1][gr][gu];
            float zj = zx1 + zp[0][gr][gu + 100] + zp[1][gr][gu + 100];
            float zf = zx2 + zp[0][gr][gu + 200] + zp[1][gr][gu + 200];
            float zo = zx3 + zp[0][gr][gu + 300] + zp[1][gr][gu + 300];
            cst = cst * sigm(zf + 1.0f) + sigm(zi) * mytanh(zj);
            hs[gr][gu] = mytanh(cst) * sigm(zo);
        }
        __syncthreads();

        // ---- FUSE: z2x[t] = h1[t] @ Wx2 + b2 (side output, no barrier) ----
        if (FUSE) {
            u64 pa0 = pk(bv, 0.f), pa1 = pk(bv, 0.f);
            const ulonglong2* wr = wq + c;
            #pragma unroll 5
            for (int q = 0; q < 25; q++) {
                ulonglong2 w = wr[q * G4];
                U4 h0; h0.f4 = *(const float4*)&hs[2 * kh][4 * q];
                U4 h1; h1.f4 = *(const float4*)&hs[2 * kh + 1][4 * q];
                ffma2(pa0, h0.u2.x, w.x);
                ffma2(pa0, h0.u2.y, w.y);
                ffma2(pa1, h1.u2.x, w.x);
                ffma2(pa1, h1.u2.y, w.y);
            }
            zx_out[((long long)(b0 + 2 * kh    ) * T25 + t) * G4 + c] = hsum(pa0);
            zx_out[((long long)(b0 + 2 * kh + 1) * T25 + t) * G4 + c] = hsum(pa1);
        }
    }

    // ---- FC head (layer-2 kernel only) ----
    if (!FUSE && out) {
        for (int idx = tid; idx < 4 * 128; idx += 800) {
            int r = idx / 128, j = idx % 128;
            float a = bfc1[j];
            #pragma unroll 4
            for (int k = 0; k < HID; k++)
                a += hs[r][k] * __ldg(wfc1 + k * 128 + j);
            fc1s[r][j] = a;
        }
        __syncthreads();
        if (tid < 8) {
            int r = tid / 2, cc = tid % 2;
            float a = bfc2[cc];
            #pragma unroll 8
            for (int k = 0; k < 128; k++)
                a += fc1s[r][k] * __ldg(wfc2 + k * 2 + cc);
            out[(b0 + r) * 2 + cc] = a;
        }
    }
}

// ---------------------------------------------------------------------------
extern "C" void kernel_launch(void* const* d_in, const int* in_sizes, int n_in,
                              void* d_out, int out_size)
{
    const int*   feats = (const int*)  d_in[0];
    const float* emb   = (const float*)d_in[1];
    const float* k1    = (const float*)d_in[2];
    const float* b1    = (const float*)d_in[3];
    const float* k2    = (const float*)d_in[4];
    const float* b2    = (const float*)d_in[5];
    const float* wfc1  = (const float*)d_in[6];
    const float* bfc1  = (const float*)d_in[7];
    const float* wfc2  = (const float*)d_in[8];
    const float* bfc2  = (const float*)d_in[9];
    float* out = (float*)d_out;

    float *zx1, *z2x;
    cudaGetSymbolAddress((void**)&zx1, g_zx1);
    cudaGetSymbolAddress((void**)&z2x, g_z2x);

    cudaFuncSetAttribute(inproj_kernel,
                         cudaFuncAttributeMaxDynamicSharedMemorySize, IP_SMEM_B);
    cudaFuncSetAttribute(rec_kernel<true>,
                         cudaFuncAttributeMaxDynamicSharedMemorySize, SM_FUSE);
    cudaFuncSetAttribute(rec_kernel<false>,
                         cudaFuncAttributeMaxDynamicSharedMemorySize, SM_PLAIN);

    // A: zx1 = emb[feats] @ k1[0:100] + b1
    inproj_kernel<<<128, 800, IP_SMEM_B>>>(feats, emb, k1, b1, zx1);
    // B': layer-1 recurrence + fused z2x projection
    rec_kernel<true><<<128, 800, SM_FUSE>>>(
        zx1, k1 + HID * G4, k2, b2, z2x,
        nullptr, nullptr, nullptr, nullptr, nullptr);
    // D': layer-2 recurrence + FC head
    rec_kernel<false><<<128, 800, SM_PLAIN>>>(
        z2x, k2 + HID * G4, nullptr, nullptr, nullptr,
        wfc1, bfc1, wfc2, bfc2, out);
}

// round 10
// speedup vs baseline: 1.8447x; 1.1249x over previous
#include <cuda_runtime.h>

#define T25   25
#define HID   100
#define G4    400
#define NROWS 12800           // 512*25
#define RT    832             // 26 warps: warps 0-12 = kh0, 13-25 = kh1

typedef unsigned long long u64;

__device__ float g_zx1[(size_t)NROWS * G4];
__device__ float g_z2x[(size_t)NROWS * G4];
__device__ float g_h1 [(size_t)NROWS * HID];

union U4 { float4 f4; ulonglong2 u2; };
union U2 { float2 f2; u64 u; };

__device__ __forceinline__ u64 pk(float lo, float hi) {
    u64 r; asm("mov.b64 %0, {%1,%2};" : "=l"(r) : "f"(lo), "f"(hi)); return r;
}
__device__ __forceinline__ void ffma2(u64& d, u64 a, u64 b) {
    asm("fma.rn.f32x2 %0, %1, %2, %0;" : "+l"(d) : "l"(a), "l"(b));
}
__device__ __forceinline__ float hsum(u64 v) {
    float a, b; asm("mov.b64 {%0,%1}, %2;" : "=f"(a), "=f"(b) : "l"(v)); return a + b;
}
__device__ __forceinline__ float sigm(float x)   { return 1.0f / (1.0f + __expf(-x)); }
__device__ __forceinline__ float mytanh(float x) { float e = __expf(-2.0f * x); return (1.0f - e) / (1.0f + e); }

#define BAR_ARRIVE(id) asm volatile("bar.arrive %0, %1;" :: "r"(id), "r"(RT) : "memory")
#define BAR_SYNCN(id)  asm volatile("bar.sync %0, %1;"   :: "r"(id), "r"(RT) : "memory")

// ---------------------------------------------------------------------------
// Input-projection GEMM (known-best 28us config, unchanged).
// ---------------------------------------------------------------------------
#define IP_SMEM_B ((HID * G4 + HID * 104) * 4)   // 201600 bytes

template<int NQ>
__device__ __forceinline__ void inproj_main(
    const float (*xs)[104], const float* __restrict__ wsm,
    int c, int rb, float bv, float* __restrict__ out, int row0)
{
    u64 acc[2 * NQ];
    u64 binit = pk(bv, bv);
    #pragma unroll
    for (int p = 0; p < 2 * NQ; p++) acc[p] = binit;

    #pragma unroll 2
    for (int k = 0; k < HID; k++) {
        float w = wsm[k * G4 + c];
        u64 wd = pk(w, w);
        const float* xr = &xs[k][rb];
        #pragma unroll
        for (int q = 0; q < NQ; q++) {
            U4 x; x.f4 = *(const float4*)(xr + 4 * q);
            ffma2(acc[2 * q],     x.u2.x, wd);
            ffma2(acc[2 * q + 1], x.u2.y, wd);
        }
    }
    #pragma unroll
    for (int p = 0; p < 2 * NQ; p++) {
        U2 v; v.u = acc[p];
        out[(long long)(row0 + rb + 2 * p) * G4 + c]     = v.f2.x;
        out[(long long)(row0 + rb + 2 * p + 1) * G4 + c] = v.f2.y;
    }
}

__global__ void __launch_bounds__(800, 1) inproj_kernel(
    const float* __restrict__ src, const int* __restrict__ feats,
    const float* __restrict__ emb, const float* __restrict__ W,
    const float* __restrict__ bias, float* __restrict__ out)
{
    extern __shared__ __align__(16) float smp[];
    float* wsm = smp;
    float (*xs)[104] = (float(*)[104])(smp + HID * G4);

    const int tid  = threadIdx.x;
    const int row0 = blockIdx.x * 100;

    for (int i4 = tid; i4 < HID * G4 / 4; i4 += 800)
        ((float4*)wsm)[i4] = ((const float4*)W)[i4];

    for (int idx = tid; idx < 25 * 100; idx += 800) {
        int j4 = idx / 100, rl = idx % 100;
        const float* base = feats
            ? emb + (long long)__ldg(feats + row0 + rl) * HID
            : src + (long long)(row0 + rl) * HID;
        float4 v = *(const float4*)(base + 4 * j4);
        xs[4 * j4 + 0][rl] = v.x;
        xs[4 * j4 + 1][rl] = v.y;
        xs[4 * j4 + 2][rl] = v.z;
        xs[4 * j4 + 3][rl] = v.w;
    }
    __syncthreads();

    const int c  = tid % G4;
    const int rg = tid / G4;
    const float bv = bias[c];
    if (rg == 0) inproj_main<13>(xs, wsm, c, 0,  bv, out, row0);
    else         inproj_main<12>(xs, wsm, c, 52, bv, out, row0);
}

// ---------------------------------------------------------------------------
// Recurrence kernel v3: R3 dataflow; warp-aligned kh groups (13+13 warps);
// split barriers (kh1 arrives bar1 without waiting and stages next step's
// zin into double-buffered smem during the gate phase); zp packed float2.
// 128 blocks x 4 rows, weights register-resident.
// ---------------------------------------------------------------------------
__global__ void __launch_bounds__(RT, 1) rec_kernel(
    const float* __restrict__ zin,    // [12800][400]  (x-proj incl bias)
    const float* __restrict__ Wh,     // [100][400]
    float*       __restrict__ h_out,  // [12800][100] or null
    const float* __restrict__ wfc1, const float* __restrict__ bfc1,
    const float* __restrict__ wfc2, const float* __restrict__ bfc2,
    float*       __restrict__ out)    // [512][2] or null
{
    __shared__ __align__(16) float  hs[4][104];      // h state
    __shared__ __align__(16) float2 zp2[4][G4];      // packed k-half partials
    __shared__ float zsm[2][4][G4];                  // staged zin, double-buffered
    __shared__ float fc1s[4][128];

    const int tid = threadIdx.x;
    const int b0  = blockIdx.x * 4;
    const int wid = tid >> 5;
    const int kh  = (wid >= 13);
    const int c   = tid - (kh ? 416 : 0);            // 0..415
    const bool act = (c < G4);

    // register-resident recurrent weights (my k half)
    u64 wp[26];
    #pragma unroll
    for (int j = 0; j < 26; j++) {
        int k = kh * 52 + 2 * j;
        float w0 = (act && k     < HID) ? __ldg(Wh + (k    ) * G4 + c) : 0.f;
        float w1 = (act && k + 1 < HID) ? __ldg(Wh + (k + 1) * G4 + c) : 0.f;
        wp[j] = pk(w0, w1);
    }
    for (int i = tid; i < 4 * 104; i += RT) ((float*)hs)[i] = 0.f;

    const int gr = c / 100;      // gate row   (kh0 active threads)
    const int gu = c % 100;      // gate unit

    // prologue: kh1 stages zin for t=0
    if (kh && act) {
        const float* zr = zin + ((long long)(b0 + gr) * T25 + 0) * G4 + gu;
        zsm[0][0][c] = __ldg(zr);
        zsm[0][1][c] = __ldg(zr + 100);
        zsm[0][2][c] = __ldg(zr + 200);
        zsm[0][3][c] = __ldg(zr + 300);
    }
    __syncthreads();

    float cst = 0.f;

    for (int t = 0; t < T25; t++) {
        // ---- GEMM over my k half (both groups) ----
        if (act) {
            u64 a0 = 0ULL, a1 = 0ULL, a2 = 0ULL, a3 = 0ULL;
            const int kb = kh * 52;
            #pragma unroll
            for (int j4 = 0; j4 < 13; j4++) {
                U4 v0; v0.f4 = *(const float4*)&hs[0][kb + 4 * j4];
                U4 v1; v1.f4 = *(const float4*)&hs[1][kb + 4 * j4];
                U4 v2; v2.f4 = *(const float4*)&hs[2][kb + 4 * j4];
                U4 v3; v3.f4 = *(const float4*)&hs[3][kb + 4 * j4];
                ffma2(a0, v0.u2.x, wp[2 * j4]);
                ffma2(a0, v0.u2.y, wp[2 * j4 + 1]);
                ffma2(a1, v1.u2.x, wp[2 * j4]);
                ffma2(a1, v1.u2.y, wp[2 * j4 + 1]);
                ffma2(a2, v2.u2.x, wp[2 * j4]);
                ffma2(a2, v2.u2.y, wp[2 * j4 + 1]);
                ffma2(a3, v3.u2.x, wp[2 * j4]);
                ffma2(a3, v3.u2.y, wp[2 * j4 + 1]);
            }
            float* zpf = &zp2[0][c].x + kh;   // write my component
            zpf[0 * G4 * 2] = hsum(a0);
            zpf[1 * G4 * 2] = hsum(a1);
            zpf[2 * G4 * 2] = hsum(a2);
            zpf[3 * G4 * 2] = hsum(a3);
        }

        if (kh) {
            BAR_ARRIVE(1);                       // signal zp ready, don't wait
            if (act && t + 1 < T25) {            // stage next step's zin
                const float* zr = zin + ((long long)(b0 + gr) * T25 + (t + 1)) * G4 + gu;
                const int nb = (t + 1) & 1;
                zsm[nb][0][c] = __ldg(zr);
                zsm[nb][1][c] = __ldg(zr + 100);
                zsm[nb][2][c] = __ldg(zr + 200);
                zsm[nb][3][c] = __ldg(zr + 300);
            }
            BAR_SYNCN(2);                        // wait for hs update
        } else {
            BAR_SYNCN(1);                        // wait for all zp
            if (act) {
                const int bf = t & 1;
                float2 p0 = zp2[gr][gu];
                float2 p1 = zp2[gr][gu + 100];
                float2 p2 = zp2[gr][gu + 200];
                float2 p3 = zp2[gr][gu + 300];
                float zi = zsm[bf][0][c] + p0.x + p0.y;
                float zj = zsm[bf][1][c] + p1.x + p1.y;
                float zf = zsm[bf][2][c] + p2.x + p2.y;
                float zo = zsm[bf][3][c] + p3.x + p3.y;
                cst = cst * sigm(zf + 1.0f) + sigm(zi) * mytanh(zj);
                float hn = mytanh(cst) * sigm(zo);
                hs[gr][gu] = hn;
                if (h_out)
                    h_out[((long long)(b0 + gr) * T25 + t) * HID + gu] = hn;
            }
            BAR_SYNCN(2);                        // release kh1 + order hs
        }
    }

    // ---- FC head (layer-2 kernel only) ----
    if (out) {
        __syncthreads();
        for (int idx = tid; idx < 4 * 128; idx += RT) {
            int r = idx / 128, j = idx % 128;
            float a = bfc1[j];
            #pragma unroll 4
            for (int k = 0; k < HID; k++)
                a += hs[r][k] * __ldg(wfc1 + k * 128 + j);
            fc1s[r][j] = a;
        }
        __syncthreads();
        if (tid < 8) {
            int r = tid / 2, cc = tid % 2;
            float a = bfc2[cc];
            #pragma unroll 8
            for (int k = 0; k < 128; k++)
                a += fc1s[r][k] * __ldg(wfc2 + k * 2 + cc);
            out[(b0 + r) * 2 + cc] = a;
        }
    }
}

// ---------------------------------------------------------------------------
extern "C" void kernel_launch(void* const* d_in, const int* in_sizes, int n_in,
                              void* d_out, int out_size)
{
    const int*   feats = (const int*)  d_in[0];
    const float* emb   = (const float*)d_in[1];
    const float* k1    = (const float*)d_in[2];
    const float* b1    = (const float*)d_in[3];
    const float* k2    = (const float*)d_in[4];
    const float* b2    = (const float*)d_in[5];
    const float* wfc1  = (const float*)d_in[6];
    const float* bfc1  = (const float*)d_in[7];
    const float* wfc2  = (const float*)d_in[8];
    const float* bfc2  = (const float*)d_in[9];
    float* out = (float*)d_out;

    float *zx1, *z2x, *h1;
    cudaGetSymbolAddress((void**)&zx1, g_zx1);
    cudaGetSymbolAddress((void**)&z2x, g_z2x);
    cudaGetSymbolAddress((void**)&h1,  g_h1);

    cudaFuncSetAttribute(inproj_kernel,
                         cudaFuncAttributeMaxDynamicSharedMemorySize, IP_SMEM_B);

    // A: zx1 = emb[feats] @ k1[0:100] + b1
    inproj_kernel<<<128, 800, IP_SMEM_B>>>(nullptr, feats, emb, k1, b1, zx1);
    // B: layer-1 recurrence -> h1
    rec_kernel<<<128, RT>>>(zx1, k1 + HID * G4, h1,
                            nullptr, nullptr, nullptr, nullptr, nullptr);
    // C: z2x = h1 @ k2[0:100] + b2
    inproj_kernel<<<128, 800, IP_SMEM_B>>>(h1, nullptr, nullptr, k2, b2, z2x);
    // D: layer-2 recurrence + FC head
    rec_kernel<<<128, RT>>>(z2x, k2 + HID * G4, nullptr,
                            wfc1, bfc1, wfc2, bfc2, out);
}

// round 11
// speedup vs baseline: 1.8884x; 1.0237x over previous
#include <cuda_runtime.h>

#define T25   25
#define HID   100
#define G4    400
#define NROWS 12800           // 512*25
#define RT    832             // 26 warps: warps 0-12 = kh0, 13-25 = kh1

typedef unsigned long long u64;

__device__ float g_zx1[(size_t)NROWS * G4];
__device__ float g_z2x[(size_t)NROWS * G4];
__device__ float g_h1 [(size_t)NROWS * HID];

union U4 { float4 f4; ulonglong2 u2; };
union U2 { float2 f2; u64 u; };

__device__ __forceinline__ u64 pk(float lo, float hi) {
    u64 r; asm("mov.b64 %0, {%1,%2};" : "=l"(r) : "f"(lo), "f"(hi)); return r;
}
__device__ __forceinline__ void ffma2(u64& d, u64 a, u64 b) {
    asm("fma.rn.f32x2 %0, %1, %2, %0;" : "+l"(d) : "l"(a), "l"(b));
}
__device__ __forceinline__ float hsum(u64 v) {
    float a, b; asm("mov.b64 {%0,%1}, %2;" : "=f"(a), "=f"(b) : "l"(v)); return a + b;
}
__device__ __forceinline__ float sigm(float x)   { return 1.0f / (1.0f + __expf(-x)); }
__device__ __forceinline__ float mytanh(float x) { float e = __expf(-2.0f * x); return (1.0f - e) / (1.0f + e); }

#define BAR_ARRIVE(id) asm volatile("bar.arrive %0, %1;" :: "r"(id), "r"(RT) : "memory")
#define BAR_SYNCN(id)  asm volatile("bar.sync %0, %1;"   :: "r"(id), "r"(RT) : "memory")

// ---------------------------------------------------------------------------
// Input-projection GEMM. v2: batched high-MLP staging of x.
// ---------------------------------------------------------------------------
#define IP_SMEM_B ((HID * G4 + HID * 104) * 4)   // 201600 bytes

template<int NQ>
__device__ __forceinline__ void inproj_main(
    const float (*xs)[104], const float* __restrict__ wsm,
    int c, int rb, float bv, float* __restrict__ out, int row0)
{
    u64 acc[2 * NQ];
    u64 binit = pk(bv, bv);
    #pragma unroll
    for (int p = 0; p < 2 * NQ; p++) acc[p] = binit;

    #pragma unroll 2
    for (int k = 0; k < HID; k++) {
        float w = wsm[k * G4 + c];
        u64 wd = pk(w, w);
        const float* xr = &xs[k][rb];
        #pragma unroll
        for (int q = 0; q < NQ; q++) {
            U4 x; x.f4 = *(const float4*)(xr + 4 * q);
            ffma2(acc[2 * q],     x.u2.x, wd);
            ffma2(acc[2 * q + 1], x.u2.y, wd);
        }
    }
    #pragma unroll
    for (int p = 0; p < 2 * NQ; p++) {
        U2 v; v.u = acc[p];
        out[(long long)(row0 + rb + 2 * p) * G4 + c]     = v.f2.x;
        out[(long long)(row0 + rb + 2 * p + 1) * G4 + c] = v.f2.y;
    }
}

__global__ void __launch_bounds__(800, 1) inproj_kernel(
    const float* __restrict__ src, const int* __restrict__ feats,
    const float* __restrict__ emb, const float* __restrict__ W,
    const float* __restrict__ bias, float* __restrict__ out)
{
    extern __shared__ __align__(16) float smp[];
    float* wsm = smp;
    float (*xs)[104] = (float(*)[104])(smp + HID * G4);

    const int tid  = threadIdx.x;
    const int row0 = blockIdx.x * 100;

    // stage W (row-major copy, float4)
    for (int i4 = tid; i4 < HID * G4 / 4; i4 += 800)
        ((float4*)wsm)[i4] = ((const float4*)W)[i4];

    // stage x transposed with batched loads (MLP >= 4 per thread):
    // 2500 float4 tasks; thread handles idx, idx+800, idx+1600, idx+2400.
    {
        float4 v[4];
        int    jj[4], rr[4];
        bool   mm[4];
        #pragma unroll
        for (int i = 0; i < 4; i++) {
            int idx = tid + i * 800;
            mm[i] = (idx < 2500);
            jj[i] = idx / 100;
            rr[i] = idx % 100;
        }
        // issue all index + data loads back-to-back (batched by ptxas)
        const float* base[4];
        #pragma unroll
        for (int i = 0; i < 4; i++) {
            if (mm[i]) {
                base[i] = feats
                    ? emb + (long long)__ldg(feats + row0 + rr[i]) * HID
                    : src + (long long)(row0 + rr[i]) * HID;
            }
        }
        #pragma unroll
        for (int i = 0; i < 4; i++)
            if (mm[i]) v[i] = *(const float4*)(base[i] + 4 * jj[i]);
        #pragma unroll
        for (int i = 0; i < 4; i++) {
            if (mm[i]) {
                xs[4 * jj[i] + 0][rr[i]] = v[i].x;
                xs[4 * jj[i] + 1][rr[i]] = v[i].y;
                xs[4 * jj[i] + 2][rr[i]] = v[i].z;
                xs[4 * jj[i] + 3][rr[i]] = v[i].w;
            }
        }
    }
    __syncthreads();

    const int c  = tid % G4;
    const int rg = tid / G4;
    const float bv = bias[c];
    if (rg == 0) inproj_main<13>(xs, wsm, c, 0,  bv, out, row0);
    else         inproj_main<12>(xs, wsm, c, 52, bv, out, row0);
}

// ---------------------------------------------------------------------------
// Recurrence kernel (R10 74.9us structure; kh1 zero-pad j4 removed: 52/48
// k-split). Warp-aligned kh groups, split barriers, smem-staged zin,
// packed float2 zp, weights register-resident.
// ---------------------------------------------------------------------------
template<int KB, int NJ>
__device__ __forceinline__ void rec_gemm(
    const float (*hs)[104], const u64* wp, float2* zp_base, int c)
{
    u64 a0 = 0ULL, a1 = 0ULL, a2 = 0ULL, a3 = 0ULL;
    #pragma unroll
    for (int j4 = 0; j4 < NJ; j4++) {
        U4 v0; v0.f4 = *(const float4*)&hs[0][KB + 4 * j4];
        U4 v1; v1.f4 = *(const float4*)&hs[1][KB + 4 * j4];
        U4 v2; v2.f4 = *(const float4*)&hs[2][KB + 4 * j4];
        U4 v3; v3.f4 = *(const float4*)&hs[3][KB + 4 * j4];
        ffma2(a0, v0.u2.x, wp[2 * j4]);
        ffma2(a0, v0.u2.y, wp[2 * j4 + 1]);
        ffma2(a1, v1.u2.x, wp[2 * j4]);
        ffma2(a1, v1.u2.y, wp[2 * j4 + 1]);
        ffma2(a2, v2.u2.x, wp[2 * j4]);
        ffma2(a2, v2.u2.y, wp[2 * j4 + 1]);
        ffma2(a3, v3.u2.x, wp[2 * j4]);
        ffma2(a3, v3.u2.y, wp[2 * j4 + 1]);
    }
    const int kcomp = (KB == 0) ? 0 : 1;
    float* zpf = (float*)zp_base + 2 * c + kcomp;
    zpf[0 * G4 * 2] = hsum(a0);
    zpf[1 * G4 * 2] = hsum(a1);
    zpf[2 * G4 * 2] = hsum(a2);
    zpf[3 * G4 * 2] = hsum(a3);
}

__global__ void __launch_bounds__(RT, 1) rec_kernel(
    const float* __restrict__ zin,    // [12800][400]  (x-proj incl bias)
    const float* __restrict__ Wh,     // [100][400]
    float*       __restrict__ h_out,  // [12800][100] or null
    const float* __restrict__ wfc1, const float* __restrict__ bfc1,
    const float* __restrict__ wfc2, const float* __restrict__ bfc2,
    float*       __restrict__ out)    // [512][2] or null
{
    __shared__ __align__(16) float  hs[4][104];
    __shared__ __align__(16) float2 zp2[4][G4];
    __shared__ float zsm[2][4][G4];
    __shared__ float fc1s[4][128];

    const int tid = threadIdx.x;
    const int b0  = blockIdx.x * 4;
    const int wid = tid >> 5;
    const int kh  = (wid >= 13);
    const int c   = tid - (kh ? 416 : 0);            // 0..415
    const bool act = (c < G4);

    // register-resident recurrent weights: kh0 -> k 0..51, kh1 -> k 52..99
    u64 wp[26];
    #pragma unroll
    for (int j = 0; j < 26; j++) {
        int k = kh * 52 + 2 * j;
        float w0 = (act && k     < HID) ? __ldg(Wh + (k    ) * G4 + c) : 0.f;
        float w1 = (act && k + 1 < HID) ? __ldg(Wh + (k + 1) * G4 + c) : 0.f;
        wp[j] = pk(w0, w1);
    }
    for (int i = tid; i < 4 * 104; i += RT) ((float*)hs)[i] = 0.f;

    const int gr = c / 100;
    const int gu = c % 100;

    // prologue: kh1 stages zin for t=0
    if (kh && act) {
        const float* zr = zin + ((long long)(b0 + gr) * T25 + 0) * G4 + gu;
        zsm[0][0][c] = __ldg(zr);
        zsm[0][1][c] = __ldg(zr + 100);
        zsm[0][2][c] = __ldg(zr + 200);
        zsm[0][3][c] = __ldg(zr + 300);
    }
    __syncthreads();

    float cst = 0.f;

    for (int t = 0; t < T25; t++) {
        // ---- GEMM over my k half (both groups) ----
        if (act) {
            if (kh == 0) rec_gemm<0, 13>(hs, wp, &zp2[0][0], c);
            else         rec_gemm<52, 12>(hs, wp, &zp2[0][0], c);
        }

        if (kh) {
            BAR_ARRIVE(1);
            if (act && t + 1 < T25) {
                const float* zr = zin + ((long long)(b0 + gr) * T25 + (t + 1)) * G4 + gu;
                const int nb = (t + 1) & 1;
                zsm[nb][0][c] = __ldg(zr);
                zsm[nb][1][c] = __ldg(zr + 100);
                zsm[nb][2][c] = __ldg(zr + 200);
                zsm[nb][3][c] = __ldg(zr + 300);
            }
            BAR_SYNCN(2);
        } else {
            BAR_SYNCN(1);
            if (act) {
                const int bf = t & 1;
                float2 p0 = zp2[gr][gu];
                float2 p1 = zp2[gr][gu + 100];
                float2 p2 = zp2[gr][gu + 200];
                float2 p3 = zp2[gr][gu + 300];
                float zi = zsm[bf][0][c] + p0.x + p0.y;
                float zj = zsm[bf][1][c] + p1.x + p1.y;
                float zf = zsm[bf][2][c] + p2.x + p2.y;
                float zo = zsm[bf][3][c] + p3.x + p3.y;
                cst = cst * sigm(zf + 1.0f) + sigm(zi) * mytanh(zj);
                float hn = mytanh(cst) * sigm(zo);
                hs[gr][gu] = hn;
                if (h_out)
                    h_out[((long long)(b0 + gr) * T25 + t) * HID + gu] = hn;
            }
            BAR_SYNCN(2);
        }
    }

    // ---- FC head (layer-2 kernel only) ----
    if (out) {
        __syncthreads();
        for (int idx = tid; idx < 4 * 128; idx += RT) {
            int r = idx / 128, j = idx % 128;
            float a = bfc1[j];
            #pragma unroll 4
            for (int k = 0; k < HID; k++)
                a += hs[r][k] * __ldg(wfc1 + k * 128 + j);
            fc1s[r][j] = a;
        }
        __syncthreads();
        if (tid < 8) {
            int r = tid / 2, cc = tid % 2;
            float a = bfc2[cc];
            #pragma unroll 8
            for (int k = 0; k < 128; k++)
                a += fc1s[r][k] * __ldg(wfc2 + k * 2 + cc);
            out[(b0 + r) * 2 + cc] = a;
        }
    }
}

// ---------------------------------------------------------------------------
extern "C" void kernel_launch(void* const* d_in, const int* in_sizes, int n_in,
                              void* d_out, int out_size)
{
    const int*   feats = (const int*)  d_in[0];
    const float* emb   = (const float*)d_in[1];
    const float* k1    = (const float*)d_in[2];
    const float* b1    = (const float*)d_in[3];
    const float* k2    = (const float*)d_in[4];
    const float* b2    = (const float*)d_in[5];
    const float* wfc1  = (const float*)d_in[6];
    const float* bfc1  = (const float*)d_in[7];
    const float* wfc2  = (const float*)d_in[8];
    const float* bfc2  = (const float*)d_in[9];
    float* out = (float*)d_out;

    float *zx1, *z2x, *h1;
    cudaGetSymbolAddress((void**)&zx1, g_zx1);
    cudaGetSymbolAddress((void**)&z2x, g_z2x);
    cudaGetSymbolAddress((void**)&h1,  g_h1);

    cudaFuncSetAttribute(inproj_kernel,
                         cudaFuncAttributeMaxDynamicSharedMemorySize, IP_SMEM_B);

    // A: zx1 = emb[feats] @ k1[0:100] + b1
    inproj_kernel<<<128, 800, IP_SMEM_B>>>(nullptr, feats, emb, k1, b1, zx1);
    // B: layer-1 recurrence -> h1
    rec_kernel<<<128, RT>>>(zx1, k1 + HID * G4, h1,
                            nullptr, nullptr, nullptr, nullptr, nullptr);
    // C: z2x = h1 @ k2[0:100] + b2
    inproj_kernel<<<128, 800, IP_SMEM_B>>>(h1, nullptr, nullptr, k2, b2, z2x);
    // D: layer-2 recurrence + FC head
    rec_kernel<<<128, RT>>>(z2x, k2 + HID * G4, nullptr,
                            wfc1, bfc1, wfc2, bfc2, out);
}